// round 13
// baseline (speedup 1.0000x reference)
#include <cuda_runtime.h>
#include <cstdint>

#define BATCH   65536
#define D0      768
#define D1      512
#define D2      256
#define D3      128
#define NCODES  256
#define NLEVELS 4
#define BETA_F  0.25f
#define QBLOCKS 256

typedef unsigned long long ull;

// ---------------- scratch (no cudaMalloc allowed) ----------------
__device__ float g_h1[(size_t)BATCH * D1];     // 128 MB
__device__ float g_h2[(size_t)BATCH * D2];     //  64 MB
__device__ float g_z [(size_t)BATCH * D3];     //  32 MB
__device__ uint32_t g_idx[BATCH];              // packed codebook indices
__device__ float g_P[NLEVELS * NCODES * D2];   // 1 MB: P = codebooks @ dw0
__device__ float g_zb[D2];                     // zero bias (zero-initialized)
__device__ float g_loss_part[QBLOCKS];

// packed fp32x2 (quant kernel)
#define PACK2(d, lo, hi) \
    asm("mov.b64 %0, {%1, %2};" : "=l"(d) : "f"(lo), "f"(hi))
#define UNPACK2(lo, hi, v) \
    asm("mov.b64 {%0, %1}, %2;" : "=f"(lo), "=f"(hi) : "l"(v))
#define FMA2(d, a, b) \
    asm("fma.rn.f32x2 %0, %1, %2, %0;" : "+l"(d) : "l"(a), "l"(b))
#define FMA2D(d, a, b, c) \
    asm("fma.rn.f32x2 %0, %1, %2, %3;" : "=l"(d) : "l"(a), "l"(b), "l"(c))

// ---------------- scalar fp32 GEMM (R6 proven shape), 4 CTAs/SM -----------
// BM=128, BN=64, BK=16, TM=8, TN=4, 256 threads.
template <bool RELU>
__global__ __launch_bounds__(256, 4) void sgemm_bias(
    const float* __restrict__ A, const float* __restrict__ W,
    const float* __restrict__ bias, float* __restrict__ C,
    int M, int N, int K)
{
    constexpr int BK = 16;
    __shared__ __align__(16) float As[BK][128];
    __shared__ __align__(16) float Bs[BK][64];

    const int tid = threadIdx.x;
    const int tx  = tid & 15;
    const int ty  = tid >> 4;
    const int rowBase = blockIdx.y * 128;
    const int colBase = blockIdx.x * 64;

    float acc[8][4];
#pragma unroll
    for (int i = 0; i < 8; i++)
#pragma unroll
        for (int j = 0; j < 4; j++) acc[i][j] = 0.0f;

    for (int k0 = 0; k0 < K; k0 += BK) {
#pragma unroll
        for (int t = 0; t < 2; t++) {
            int f  = tid + t * 256;
            int ar = f >> 2, aq = f & 3;
            float4 v = *reinterpret_cast<const float4*>(
                &A[(size_t)(rowBase + ar) * K + k0 + aq * 4]);
            As[aq * 4 + 0][ar] = v.x;
            As[aq * 4 + 1][ar] = v.y;
            As[aq * 4 + 2][ar] = v.z;
            As[aq * 4 + 3][ar] = v.w;
        }
        {
            int br = tid >> 4, bc = tid & 15;
            float4 v = *reinterpret_cast<const float4*>(
                &W[(size_t)(k0 + br) * N + colBase + bc * 4]);
            *reinterpret_cast<float4*>(&Bs[br][bc * 4]) = v;
        }
        __syncthreads();

#pragma unroll
        for (int kk = 0; kk < BK; kk++) {
            float4 a0 = *reinterpret_cast<const float4*>(&As[kk][ty * 8]);
            float4 a1 = *reinterpret_cast<const float4*>(&As[kk][ty * 8 + 4]);
            float4 b  = *reinterpret_cast<const float4*>(&Bs[kk][tx * 4]);
            float a[8] = {a0.x, a0.y, a0.z, a0.w, a1.x, a1.y, a1.z, a1.w};
#pragma unroll
            for (int i = 0; i < 8; i++) {
                acc[i][0] += a[i] * b.x;
                acc[i][1] += a[i] * b.y;
                acc[i][2] += a[i] * b.z;
                acc[i][3] += a[i] * b.w;
            }
        }
        __syncthreads();
    }

    float4 bv = *reinterpret_cast<const float4*>(&bias[colBase + tx * 4]);
#pragma unroll
    for (int i = 0; i < 8; i++) {
        int r = rowBase + ty * 8 + i;
        float4 o;
        o.x = acc[i][0] + bv.x;
        o.y = acc[i][1] + bv.y;
        o.z = acc[i][2] + bv.z;
        o.w = acc[i][3] + bv.w;
        if (RELU) {
            o.x = fmaxf(o.x, 0.0f); o.y = fmaxf(o.y, 0.0f);
            o.z = fmaxf(o.z, 0.0f); o.w = fmaxf(o.w, 0.0f);
        }
        *reinterpret_cast<float4*>(&C[(size_t)r * N + colBase + tx * 4]) = o;
    }
}

// ---------------- fused residual quantization -> packed indices ------------
__global__ __launch_bounds__(256) void quant_all(
    const float* __restrict__ z, const float* __restrict__ codebooks,
    uint32_t* __restrict__ idxOut, float* __restrict__ partials)
{
    __shared__ __align__(16) float sC[64 * D3];
    __shared__ float snorm[64];
    __shared__ float sred[256];

    const int tid = threadIdx.x;
    const size_t row = (size_t)blockIdx.x * 256 + tid;

    ull r2[64];
    {
        const ulonglong2* zp = reinterpret_cast<const ulonglong2*>(z + row * D3);
#pragma unroll
        for (int k = 0; k < 32; k++) {
            ulonglong2 v = zp[k];
            r2[2 * k] = v.x; r2[2 * k + 1] = v.y;
        }
    }
    ull mone; PACK2(mone, -1.0f, -1.0f);
    ull ls0 = 0ULL, ls1 = 0ULL;
    uint32_t packed = 0;

    for (int l = 0; l < NLEVELS; l++) {
        const float* C = codebooks + (size_t)l * NCODES * D3;
        float best = 3.4e38f;
        int bi = 0;

        for (int ch = 0; ch < 4; ch++) {
            __syncthreads();
            const float4* src =
                reinterpret_cast<const float4*>(C + (size_t)ch * 64 * D3);
            float4* dst = reinterpret_cast<float4*>(sC);
#pragma unroll
            for (int i = 0; i < 8; i++) dst[tid + i * 256] = src[tid + i * 256];
            __syncthreads();
            if (tid < 64) {
                const float4* cp = reinterpret_cast<const float4*>(sC + tid * D3);
                float s = 0.0f;
#pragma unroll
                for (int i = 0; i < 32; i++) {
                    float4 v = cp[i];
                    s += v.x * v.x + v.y * v.y + v.z * v.z + v.w * v.w;
                }
                snorm[tid] = s;
            }
            __syncthreads();

            for (int c = 0; c < 64; c++) {
                const ulonglong2* cp =
                    reinterpret_cast<const ulonglong2*>(sC + c * D3);
                ull a0 = 0ULL, a1 = 0ULL;
#pragma unroll
                for (int k = 0; k < 32; k++) {
                    ulonglong2 v = cp[k];
                    FMA2(a0, r2[2 * k],     v.x);
                    FMA2(a1, r2[2 * k + 1], v.y);
                }
                float s0, s1, s2, s3;
                UNPACK2(s0, s1, a0);
                UNPACK2(s2, s3, a1);
                float dot = (s0 + s1) + (s2 + s3);
                float score = snorm[c] - 2.0f * dot;
                if (score < best) { best = score; bi = ch * 64 + c; }
            }
        }

        packed |= (uint32_t)bi << (8 * l);

        const ulonglong2* qp =
            reinterpret_cast<const ulonglong2*>(C + (size_t)bi * D3);
#pragma unroll
        for (int k = 0; k < 32; k++) {
            ulonglong2 q = qp[k];
            ull d0, d1;
            FMA2D(d0, q.x, mone, r2[2 * k]);      // r - q
            FMA2D(d1, q.y, mone, r2[2 * k + 1]);
            FMA2(ls0, d0, d0);
            FMA2(ls1, d1, d1);
            r2[2 * k] = d0; r2[2 * k + 1] = d1;
        }
    }

    idxOut[row] = packed;

    float s0, s1, s2, s3;
    UNPACK2(s0, s1, ls0);
    UNPACK2(s2, s3, ls1);
    sred[tid] = (s0 + s1) + (s2 + s3);
    __syncthreads();
#pragma unroll
    for (int s = 128; s > 0; s >>= 1) {
        if (tid < s) sred[tid] += sred[tid + s];
        __syncthreads();
    }
    if (tid == 0) partials[blockIdx.x] = sred[0];
}

// ---------------- dec1 via lookup: h2 = relu(Σ_l P[l][idx_l] + db0) --------
// 8 threads per row, 32 cols each; block=256 -> 32 rows.
__global__ __launch_bounds__(256) void dec1_lookup(
    const uint32_t* __restrict__ idx, const float* __restrict__ P,
    const float* __restrict__ bias, float* __restrict__ h2)
{
    const int tid = threadIdx.x;
    const int row = blockIdx.x * 32 + (tid >> 3);
    const int c0  = (tid & 7) * 32;

    uint32_t iw = idx[row];
    float4 acc[8];
    const float4* bp = reinterpret_cast<const float4*>(bias + c0);
#pragma unroll
    for (int j = 0; j < 8; j++) acc[j] = bp[j];

#pragma unroll
    for (int l = 0; l < NLEVELS; l++) {
        int code = (iw >> (8 * l)) & 255;
        const float4* pp = reinterpret_cast<const float4*>(
            P + ((size_t)(l * NCODES + code) * D2) + c0);
#pragma unroll
        for (int j = 0; j < 8; j++) {
            float4 v = pp[j];
            acc[j].x += v.x; acc[j].y += v.y;
            acc[j].z += v.z; acc[j].w += v.w;
        }
    }

    float4* op = reinterpret_cast<float4*>(h2 + (size_t)row * D2 + c0);
#pragma unroll
    for (int j = 0; j < 8; j++) {
        float4 o = acc[j];
        o.x = fmaxf(o.x, 0.f); o.y = fmaxf(o.y, 0.f);
        o.z = fmaxf(o.z, 0.f); o.w = fmaxf(o.w, 0.f);
        op[j] = o;
    }
}

// ---------------- deterministic loss finalize ----------------
__global__ void finalize_loss(const float* __restrict__ partials,
                              float* __restrict__ out)
{
    if (threadIdx.x == 0 && blockIdx.x == 0) {
        float tot = 0.0f;
        for (int i = 0; i < QBLOCKS; i++) tot += partials[i];
        float rq = (1.0f + BETA_F) * tot /
                   ((float)NLEVELS * (float)BATCH * (float)D3);
        *out = rq;
    }
}

// ---------------- launch ----------------
extern "C" void kernel_launch(void* const* d_in, const int* in_sizes, int n_in,
                              void* d_out, int out_size)
{
    (void)in_sizes; (void)n_in;
    const float* x   = (const float*)d_in[0];
    const float* ew0 = (const float*)d_in[1];
    const float* eb0 = (const float*)d_in[2];
    const float* ew1 = (const float*)d_in[3];
    const float* eb1 = (const float*)d_in[4];
    const float* ew2 = (const float*)d_in[5];
    const float* eb2 = (const float*)d_in[6];
    const float* dw0 = (const float*)d_in[7];
    const float* db0 = (const float*)d_in[8];
    const float* dw1 = (const float*)d_in[9];
    const float* db1 = (const float*)d_in[10];
    const float* dw2 = (const float*)d_in[11];
    const float* db2 = (const float*)d_in[12];
    const float* cb  = (const float*)d_in[13];
    float* out = (float*)d_out;

    float *h1, *h2, *z, *P, *zb, *lp;
    uint32_t* idx;
    cudaGetSymbolAddress((void**)&h1,  g_h1);
    cudaGetSymbolAddress((void**)&h2,  g_h2);
    cudaGetSymbolAddress((void**)&z,   g_z);
    cudaGetSymbolAddress((void**)&idx, g_idx);
    cudaGetSymbolAddress((void**)&P,   g_P);
    cudaGetSymbolAddress((void**)&zb,  g_zb);
    cudaGetSymbolAddress((void**)&lp,  g_loss_part);

    const int MB = BATCH / 128;

    // P = codebooks @ dw0   (M=1024, N=256, K=128; zero bias, no relu)
    sgemm_bias<false><<<dim3(D2 / 64, (NLEVELS * NCODES) / 128), 256>>>(
        cb, dw0, zb, P, NLEVELS * NCODES, D2, D3);

    // encoder
    sgemm_bias<true ><<<dim3(D1 / 64, MB), 256>>>(x,  ew0, eb0, h1, BATCH, D1, D0);
    sgemm_bias<true ><<<dim3(D2 / 64, MB), 256>>>(h1, ew1, eb1, h2, BATCH, D2, D1);
    sgemm_bias<false><<<dim3(D3 / 64, MB), 256>>>(h2, ew2, eb2, z,  BATCH, D3, D2);

    // fused residual quantization -> indices + loss partials
    quant_all<<<QBLOCKS, 256>>>(z, cb, idx, lp);

    // dec1 replaced by table lookup (h2 = relu(x_q @ dw0 + db0))
    dec1_lookup<<<BATCH / 32, 256>>>(idx, P, db0, h2);

    // dec2, dec3
    sgemm_bias<true ><<<dim3(D1 / 64, MB), 256>>>(h2, dw1, db1, h1,  BATCH, D1, D2);
    sgemm_bias<false><<<dim3(D0 / 64, MB), 256>>>(h1, dw2, db2, out, BATCH, D0, D1);

    finalize_loss<<<1, 32>>>(lp, out + (size_t)out_size - 1);
}